// round 11
// baseline (speedup 1.0000x reference)
#include <cuda_runtime.h>
#include <cuda_bf16.h>

typedef unsigned long long u64;

// Problem constants
#define B_   16
#define K_   256
#define T_   64
#define D_   128
// e = C_LIN*(P+Q) + C_ABS*sum_d a_d*|u+vb| + bias   (alpha = 0.2)
#define C_LIN 0.6f
#define C_ABS 0.4f
#define ABSMASK2 0x7FFFFFFF7FFFFFFFULL

__device__ __forceinline__ u64 addx2(u64 a, u64 b) {
    u64 r; asm("add.rn.f32x2 %0,%1,%2;" : "=l"(r) : "l"(a), "l"(b)); return r;
}
__device__ __forceinline__ u64 fmax2p(u64 a, u64 b, u64 c) {
    u64 r; asm("fma.rn.f32x2 %0,%1,%2,%3;" : "=l"(r) : "l"(a), "l"(b), "l"(c)); return r;
}
__device__ __forceinline__ u64 dup2(float v) {
    u64 r; asm("mov.b64 %0, {%1, %1};" : "=l"(r) : "f"(v)); return r;
}
__device__ __forceinline__ u64 pack2(float lo, float hi) {
    u64 r; asm("mov.b64 %0, {%1, %2};" : "=l"(r) : "f"(lo), "f"(hi)); return r;
}
__device__ __forceinline__ float lo32(u64 v) { return __uint_as_float((unsigned)v); }
__device__ __forceinline__ float hi32(u64 v) { return __uint_as_float((unsigned)(v >> 32)); }

// Scratch (device globals: allocation-free rule)
__device__ float g_U [B_*K_*D_];      // u[b,k,d]
__device__ float g_Vb[B_*K_*D_];      // v[b,k,d] + b_lin[d]
__device__ float g_P [B_*K_];         // sum_d a_d * u
__device__ float g_Q [B_*K_];         // sum_d a_d * vb
__device__ float g_Hp[2*B_*K_*T_];    // partial unnormalized h, per j-half
__device__ float g_Sp[2*B_*K_];       // partial softmax sums, per j-half

// ---------------------------------------------------------------------------
// Kernel A v4: lane = row, warp = 16 cols; W read via warp-uniform LDG
// (L1 broadcast, no smem staging). 128 blocks x 512 threads, smem 44 KB.
// ---------------------------------------------------------------------------
#define XT_STRIDE 33
#define OB_STRIDE 257
#define KA_XT_OFF 0
#define KA_RP_OFF (64*XT_STRIDE)            // 2112 (8 x 33)
#define KA_RQ_OFF (KA_RP_OFF + 8*33)        // 2376
#define KA_OB_OFF (KA_RQ_OFF + 8*33)        // 2640 (32 x 257)
#define KA_SMEM_FLOATS (KA_OB_OFF + 32*OB_STRIDE)   // 10864 floats = 43456 B

__global__ void __launch_bounds__(512)
kA(const float* __restrict__ x, const float* __restrict__ W,
   const float* __restrict__ b_lin, const float* __restrict__ a)
{
    extern __shared__ float sm[];
    float* xst  = sm + KA_XT_OFF;     // xst[k*33 + row]
    float* redP = sm + KA_RP_OFF;
    float* redQ = sm + KA_RQ_OFF;
    float* outB = sm + KA_OB_OFF;

    const int tid  = threadIdx.x;
    const int row0 = blockIdx.x * 32;

    for (int idx = tid; idx < 32*64; idx += 512) {
        const int r = idx >> 6, k = idx & 63;
        xst[k*XT_STRIDE + r] = x[(row0 + r)*T_ + k];
    }
    __syncthreads();

    const int l  = tid & 31;       // lane = local row
    const int w  = tid >> 5;       // warp -> cols [16w, 16w+16)
    const int c0 = w * 16;
    const float* wbase = (w < 8) ? (W + c0*128) : (W + (c0 - 128)*128 + 64);

    u64 acc[16];
    #pragma unroll
    for (int cc = 0; cc < 16; cc++) acc[cc] = 0ull;

    #pragma unroll 2
    for (int k4 = 0; k4 < 16; k4++) {
        const u64 xp01 = pack2(xst[(4*k4 + 0)*XT_STRIDE + l],
                               xst[(4*k4 + 1)*XT_STRIDE + l]);
        const u64 xp23 = pack2(xst[(4*k4 + 2)*XT_STRIDE + l],
                               xst[(4*k4 + 3)*XT_STRIDE + l]);
        #pragma unroll
        for (int cq = 0; cq < 4; cq++) {
            float4 wv[4];
            #pragma unroll
            for (int cc = 0; cc < 4; cc++)
                wv[cc] = __ldg((const float4*)(wbase + (4*cq + cc)*128 + 4*k4));
            #pragma unroll
            for (int cc = 0; cc < 4; cc++) {
                const u64* wp = (const u64*)&wv[cc];
                acc[4*cq + cc] = fmax2p(xp01, wp[0], acc[4*cq + cc]);
                acc[4*cq + cc] = fmax2p(xp23, wp[1], acc[4*cq + cc]);
            }
        }
    }

    // finalize: b_lin for V-cols, P/Q partials, stash to outB (stride 257)
    {
        float pq = 0.f;
        const bool isV = (w >= 8);
        #pragma unroll
        for (int cc = 0; cc < 16; cc++) {
            const int c = c0 + cc;
            float sv = lo32(acc[cc]) + hi32(acc[cc]);
            if (isV) sv += __ldg(b_lin + c - 128);
            outB[l*OB_STRIDE + c] = sv;
            pq = fmaf(__ldg(a + (c & 127)), sv, pq);
        }
        if (isV) redQ[(w - 8)*33 + l] = pq;
        else     redP[w*33 + l]       = pq;
    }
    __syncthreads();

    if (tid < 32) {
        float p = 0.f;
        #pragma unroll
        for (int ww = 0; ww < 8; ww++) p += redP[ww*33 + tid];
        g_P[row0 + tid] = p;
    } else if (tid < 64) {
        const int r = tid - 32;
        float q = 0.f;
        #pragma unroll
        for (int ww = 0; ww < 8; ww++) q += redQ[ww*33 + r];
        g_Q[row0 + r] = q;
    }

    for (int idx = tid; idx < 32*256; idx += 512) {
        const int r = idx >> 8, c = idx & 255;
        const float val = outB[r*OB_STRIDE + c];
        if (c < 128) g_U [(row0 + r)*D_ + c]       = val;
        else         g_Vb[(row0 + r)*D_ + c - 128] = val;
    }
}

// ---------------------------------------------------------------------------
// Kernel B1: j-split half-block. Grid (8 ig, 16 b, 2 jh) x 512 thr,
// smem 103.6 KB -> 2 blocks/SM. Computes raw-exp weights for its 128 j,
// partial S, and unnormalized partial h -> g_Hp/g_Sp.
// ---------------------------------------------------------------------------
#define HVBS_F   (128*132)                  // 16896
#define HUS_OFF  HVBS_F                     // 16896
#define HAS_OFF  (HUS_OFF + 32*132)         // 21120
#define HQS_OFF  (HAS_OFF + 128)            // 21248
#define HPS_OFF  (HQS_OFF + 128)            // 21376
#define HSR_OFF  (HPS_OFF + 32)             // 21408 (16*32)
#define HWS_OFF  (HSR_OFF + 512)            // 21920 (128*36)
#define B1_SMEM_FLOATS (HWS_OFF + 128*36)   // 26528 floats = 106112 B
#define HHR_OFF  8192                       // hred overlay after x-half

__global__ void __launch_bounds__(512, 2)
kB1(const float* __restrict__ x, const float* __restrict__ a,
    const float* __restrict__ bias)
{
    extern __shared__ float sm[];
    float* Vbs  = sm;            // 128 j-rows of this half
    float* Us   = sm + HUS_OFF;
    float* as_  = sm + HAS_OFF;
    float* Qs   = sm + HQS_OFF;  // this half's Q
    float* Ps   = sm + HPS_OFF;
    float* sred = sm + HSR_OFF;
    float* ws   = sm + HWS_OFF;  // raw exp weights, ws[jl*36 + il]

    const int tid = threadIdx.x;
    const int b   = blockIdx.y;
    const int jh  = blockIdx.z;          // j-half
    const int igbase = blockIdx.x * 32;
    const int jgbase = jh * 128;

    // ---- stage Vb half, 32 U rows, a, Q-half, P ----
    {
        const float4* vg4  = (const float4*)g_Vb + (b*K_ + jgbase) * (D_/4);
        float4*       vbs4 = (float4*)Vbs;
        for (int idx = tid; idx < 128*D_/4; idx += 512) {
            const int j = idx >> 5, c = idx & 31;
            vbs4[j*33 + c] = vg4[idx];
        }
        const float4* ug4 = (const float4*)g_U + (b*K_ + igbase) * (D_/4);
        float4*       us4 = (float4*)Us;
        for (int idx = tid; idx < 32*D_/4; idx += 512) {
            const int il = idx >> 5, c = idx & 31;
            us4[il*33 + c] = ug4[idx];
        }
        if (tid < 128) as_[tid] = a[tid];
        else if (tid < 256) Qs[tid - 128] = g_Q[b*K_ + jgbase + tid - 128];
        else if (tid < 288) Ps[tid - 256] = g_P[b*K_ + igbase + tid - 256];
    }

    const int w  = tid >> 5;         // 0..15
    const int l  = tid & 31;         // lane = local i row
    const int j0 = w * 8;            // warp's local j chunk

    const float4* brow4 = (const float4*)(bias + (igbase + l)*K_ + jgbase + j0);
    const float4 bv0 = __ldg(brow4);
    const float4 bv1 = __ldg(brow4 + 1);

    __syncthreads();   // B1

    // ---- e-loop: acc[jj] = packed sum_d a_d * |u_{l,d} + vb_{j0+jj,d}| ----
    u64 acc[8];
    #pragma unroll
    for (int jj = 0; jj < 8; jj++) acc[jj] = 0ull;

    {
        const ulonglong2* vbs2 = (const ulonglong2*)Vbs;
        const ulonglong2* us2  = (const ulonglong2*)Us;
        const ulonglong2* a2   = (const ulonglong2*)as_;
        for (int dc = 0; dc < 32; dc++) {
            const ulonglong2 uv = us2[l*33 + dc];
            const ulonglong2 av = a2[dc];
            ulonglong2 vv[8];
            #pragma unroll
            for (int jj = 0; jj < 8; jj++) vv[jj] = vbs2[(j0 + jj)*33 + dc];
            #pragma unroll
            for (int jj = 0; jj < 8; jj++) {
                u64 z;
                z = addx2(uv.x, vv[jj].x); acc[jj] = fmax2p(av.x, z & ABSMASK2, acc[jj]);
                z = addx2(uv.y, vv[jj].y); acc[jj] = fmax2p(av.y, z & ABSMASK2, acc[jj]);
            }
        }
    }

    // ---- raw exp weights + warp-partial sums ----
    {
        const float P = Ps[l];
        const float bb[8] = {bv0.x, bv0.y, bv0.z, bv0.w, bv1.x, bv1.y, bv1.z, bv1.w};
        float s = 0.f;
        float e[8];
        #pragma unroll
        for (int jj = 0; jj < 8; jj++) {
            const float A  = lo32(acc[jj]) + hi32(acc[jj]);
            const float ev = fmaf(C_LIN, P + Qs[j0 + jj], fmaf(C_ABS, A, bb[jj]));
            e[jj] = __expf(ev);
            s += e[jj];
        }
        sred[w*32 + l] = s;
        #pragma unroll
        for (int jj = 0; jj < 8; jj++)
            ws[(j0 + jj)*36 + l] = e[jj];
    }
    __syncthreads();   // B2 — Vbs dead

    // ---- overlay x[b, this j-half] onto dead Vbs ----
    {
        float4*       xs4 = (float4*)sm;
        const float4* xg4 = (const float4*)x + (b*K_ + jgbase) * (T_/4);
        for (int idx = tid; idx < 128*T_/4; idx += 512) xs4[idx] = xg4[idx];
    }
    __syncthreads();   // B3

    // ---- epilogue stage 1: warp = (4 i's, 64 of the 128 j); -> hred ----
    u64* hred = (u64*)(sm + HHR_OFF);    // hred[(i*2 + c)*33 + l]
    {
        const int g = w & 7;             // i-group: i = 4g..4g+3
        const int c = w >> 3;            // local j chunk [64c, 64c+64)
        const u64* xs2 = (const u64*)sm;
        u64 h[4] = {0ull, 0ull, 0ull, 0ull};
        const int jbeg = 64*c;
        #pragma unroll 8
        for (int j = jbeg; j < jbeg + 64; j++) {
            const u64    xv = xs2[j*32 + l];
            const float4 wq = *(const float4*)(ws + j*36 + 4*g);   // broadcast
            h[0] = fmax2p(dup2(wq.x), xv, h[0]);
            h[1] = fmax2p(dup2(wq.y), xv, h[1]);
            h[2] = fmax2p(dup2(wq.z), xv, h[2]);
            h[3] = fmax2p(dup2(wq.w), xv, h[3]);
        }
        #pragma unroll
        for (int ii = 0; ii < 4; ii++)
            hred[((4*g + ii)*2 + c)*33 + l] = h[ii];
    }
    __syncthreads();   // B4

    // ---- stage 2: warp w -> i rows {w, w+16}; combine + store partials ----
    #pragma unroll
    for (int rep = 0; rep < 2; rep++) {
        const int i = w + 16*rep;
        u64 h = addx2(hred[(i*2 + 0)*33 + l], hred[(i*2 + 1)*33 + l]);
        float S = sred[i];
        #pragma unroll
        for (int wp = 1; wp < 16; wp++) S += sred[wp*32 + i];
        const int row = b*K_ + igbase + i;
        float2 o; o.x = lo32(h); o.y = hi32(h);
        *(float2*)(g_Hp + jh*(B_*K_*T_) + row*T_ + 2*l) = o;
        if (l == 0) g_Sp[jh*(B_*K_) + row] = S;
    }
}

// ---------------------------------------------------------------------------
// Kernel C: combine halves, normalize, sigmoid. 128 blocks x 512 thr.
// ---------------------------------------------------------------------------
__global__ void __launch_bounds__(512)
kC(float* __restrict__ out)
{
    const int gid = blockIdx.x * 512 + threadIdx.x;     // 65536 float4s
    const float4 h0 = ((const float4*)g_Hp)[gid];
    const float4 h1 = ((const float4*)g_Hp)[gid + (B_*K_*T_/4)];
    const int row = gid >> 4;
    const float inv = __fdividef(1.f, g_Sp[row] + g_Sp[B_*K_ + row]);
    float4 o;
    o.x = __fdividef(1.f, 1.f + __expf(-(h0.x + h1.x) * inv));
    o.y = __fdividef(1.f, 1.f + __expf(-(h0.y + h1.y) * inv));
    o.z = __fdividef(1.f, 1.f + __expf(-(h0.z + h1.z) * inv));
    o.w = __fdividef(1.f, 1.f + __expf(-(h0.w + h1.w) * inv));
    ((float4*)out)[gid] = o;
}

// ---------------------------------------------------------------------------
extern "C" void kernel_launch(void* const* d_in, const int* in_sizes, int n_in,
                              void* d_out, int out_size)
{
    const float* x     = (const float*)d_in[0];
    // d_in[1] = embedding (unused by the reference computation)
    const float* W     = (const float*)d_in[2];
    const float* b_lin = (const float*)d_in[3];
    const float* a     = (const float*)d_in[4];
    const float* bias  = (const float*)d_in[5];
    float* out = (float*)d_out;

    const int smemA  = KA_SMEM_FLOATS * 4;   // 43456 B
    const int smemB1 = B1_SMEM_FLOATS * 4;   // 106112 B
    cudaFuncSetAttribute(kA,  cudaFuncAttributeMaxDynamicSharedMemorySize, smemA);
    cudaFuncSetAttribute(kB1, cudaFuncAttributeMaxDynamicSharedMemorySize, smemB1);

    kA<<<128, 512, smemA>>>(x, W, b_lin, a);
    kB1<<<dim3(8, 16, 2), 512, smemB1>>>(x, a, bias);
    kC<<<128, 512>>>(out);
}

// round 12
// speedup vs baseline: 1.0453x; 1.0453x over previous
#include <cuda_runtime.h>
#include <cuda_bf16.h>

typedef unsigned long long u64;

// Problem constants
#define B_   16
#define K_   256
#define T_   64
#define D_   128
// e = C_LIN*(P+Q) + C_ABS*sum_d a_d*|u+vb| + bias   (alpha = 0.2)
#define C_LIN 0.6f
#define C_ABS 0.4f
#define ABSMASK2 0x7FFFFFFF7FFFFFFFULL

__device__ __forceinline__ u64 addx2(u64 a, u64 b) {
    u64 r; asm("add.rn.f32x2 %0,%1,%2;" : "=l"(r) : "l"(a), "l"(b)); return r;
}
__device__ __forceinline__ u64 fmax2p(u64 a, u64 b, u64 c) {
    u64 r; asm("fma.rn.f32x2 %0,%1,%2,%3;" : "=l"(r) : "l"(a), "l"(b), "l"(c)); return r;
}
__device__ __forceinline__ u64 dup2(float v) {
    u64 r; asm("mov.b64 %0, {%1, %1};" : "=l"(r) : "f"(v)); return r;
}
__device__ __forceinline__ u64 pack2(float lo, float hi) {
    u64 r; asm("mov.b64 %0, {%1, %2};" : "=l"(r) : "f"(lo), "f"(hi)); return r;
}
__device__ __forceinline__ float lo32(u64 v) { return __uint_as_float((unsigned)v); }
__device__ __forceinline__ float hi32(u64 v) { return __uint_as_float((unsigned)(v >> 32)); }

// Scratch (device globals: allocation-free rule)
__device__ float g_U [B_*K_*D_];      // u[b,k,d]
__device__ float g_Vb[B_*K_*D_];      // v[b,k,d] + b_lin[d]
__device__ float g_P [B_*K_];         // sum_d a_d * u
__device__ float g_Q [B_*K_];         // sum_d a_d * vb
__device__ float g_Hp[2*B_*K_*T_];    // partial unnormalized h, per j-half
__device__ float g_Sp[2*B_*K_];       // partial softmax sums, per j-half

// ---------------------------------------------------------------------------
// Kernel A (v3, reverted from R11's LDG regression): lane = row, warp = 16
// output cols; W staged in smem, read BROADCAST (LDS). x transposed in smem.
// Writeback through an smem transpose (stride 257). 128 blocks x 512 threads.
// ---------------------------------------------------------------------------
#define WS_STRIDE 68
#define XT_STRIDE 33
#define OB_STRIDE 257
#define KA_W_F    (256*WS_STRIDE)            // 17408
#define KA_XT_OFF (KA_W_F)                   // 64 x 33 = 2112
#define KA_AS_OFF (KA_XT_OFF + 64*XT_STRIDE) // 19520
#define KA_BL_OFF (KA_AS_OFF + 128)          // 19648
#define KA_RP_OFF (KA_BL_OFF + 128)          // 19776  (8 x 33)
#define KA_RQ_OFF (KA_RP_OFF + 8*33)         // 20040
#define KA_SMEM_FLOATS (KA_RQ_OFF + 8*33)    // 20304 floats = 81216 B

__global__ void __launch_bounds__(512)
kA(const float* __restrict__ x, const float* __restrict__ W,
   const float* __restrict__ b_lin, const float* __restrict__ a)
{
    extern __shared__ float sm[];
    float* Ws   = sm;                 // Wr[c][t], c = 0..255 (c<128 -> W1, else W2)
    float* xst  = sm + KA_XT_OFF;     // xst[k*33 + row]
    float* asA  = sm + KA_AS_OFF;
    float* bls  = sm + KA_BL_OFF;
    float* redP = sm + KA_RP_OFF;
    float* redQ = sm + KA_RQ_OFF;
    float* outB = sm;                 // overlay on Ws after main loop

    const int tid  = threadIdx.x;
    const int row0 = blockIdx.x * 32;

    for (int idx = tid; idx < 256*64; idx += 512) {
        const int n = idx >> 6, t = idx & 63;
        Ws[n*WS_STRIDE + t] = (n < 128) ? W[n*128 + t] : W[(n-128)*128 + 64 + t];
    }
    for (int idx = tid; idx < 32*64; idx += 512) {
        const int r = idx >> 6, k = idx & 63;
        xst[k*XT_STRIDE + r] = x[(row0 + r)*T_ + k];
    }
    if (tid < 128) asA[tid] = a[tid];
    else if (tid >= 256 && tid < 384) bls[tid - 256] = b_lin[tid - 256];
    __syncthreads();

    const int l  = tid & 31;       // lane = local row
    const int w  = tid >> 5;       // warp -> cols [16w, 16w+16)
    const int c0 = w * 16;

    u64 acc[16];
    #pragma unroll
    for (int cc = 0; cc < 16; cc++) acc[cc] = 0ull;

    #pragma unroll 4
    for (int k4 = 0; k4 < 16; k4++) {
        const float x0 = xst[(4*k4 + 0)*XT_STRIDE + l];
        const float x1 = xst[(4*k4 + 1)*XT_STRIDE + l];
        const float x2 = xst[(4*k4 + 2)*XT_STRIDE + l];
        const float x3 = xst[(4*k4 + 3)*XT_STRIDE + l];
        const u64 xp01 = pack2(x0, x1);
        const u64 xp23 = pack2(x2, x3);
        #pragma unroll
        for (int cc = 0; cc < 16; cc++) {
            const ulonglong2 wv = *(const ulonglong2*)(Ws + (c0 + cc)*WS_STRIDE + 4*k4);
            acc[cc] = fmax2p(xp01, wv.x, acc[cc]);
            acc[cc] = fmax2p(xp23, wv.y, acc[cc]);
        }
    }
    __syncthreads();   // all Ws reads done before outB overlay

    // finalize: add b_lin for V-cols, P/Q partials, stash to outB (stride 257)
    {
        float pq = 0.f;
        const bool isV = (w >= 8);
        #pragma unroll
        for (int cc = 0; cc < 16; cc++) {
            const int c  = c0 + cc;
            float sv = lo32(acc[cc]) + hi32(acc[cc]);
            if (isV) sv += bls[c - 128];
            outB[l*OB_STRIDE + c] = sv;
            pq = fmaf(asA[c & 127], sv, pq);
        }
        if (isV) redQ[(w - 8)*33 + l] = pq;
        else     redP[w*33 + l]       = pq;
    }
    __syncthreads();

    // P/Q combine
    if (tid < 32) {
        float p = 0.f;
        #pragma unroll
        for (int ww = 0; ww < 8; ww++) p += redP[ww*33 + tid];
        g_P[row0 + tid] = p;
    } else if (tid < 64) {
        const int r = tid - 32;
        float q = 0.f;
        #pragma unroll
        for (int ww = 0; ww < 8; ww++) q += redQ[ww*33 + r];
        g_Q[row0 + r] = q;
    }

    // coalesced writeback
    for (int idx = tid; idx < 32*256; idx += 512) {
        const int r = idx >> 8, c = idx & 255;
        const float val = outB[r*OB_STRIDE + c];
        if (c < 128) g_U [(row0 + r)*D_ + c]       = val;
        else         g_Vb[(row0 + r)*D_ + c - 128] = val;
    }
}

// ---------------------------------------------------------------------------
// Kernel B1: j-split half-block (kept from R11 — the win). Grid (8,16,2) x
// 512 thr, smem 106 KB -> 2 blocks/SM. Raw-exp weights for its 128 j,
// partial S, unnormalized partial h -> g_Hp/g_Sp.
// ---------------------------------------------------------------------------
#define HVBS_F   (128*132)                  // 16896
#define HUS_OFF  HVBS_F                     // 16896
#define HAS_OFF  (HUS_OFF + 32*132)         // 21120
#define HQS_OFF  (HAS_OFF + 128)            // 21248
#define HPS_OFF  (HQS_OFF + 128)            // 21376
#define HSR_OFF  (HPS_OFF + 32)             // 21408 (16*32)
#define HWS_OFF  (HSR_OFF + 512)            // 21920 (128*36)
#define B1_SMEM_FLOATS (HWS_OFF + 128*36)   // 26528 floats = 106112 B
#define HHR_OFF  8192                       // hred overlay after x-half

__global__ void __launch_bounds__(512, 2)
kB1(const float* __restrict__ x, const float* __restrict__ a,
    const float* __restrict__ bias)
{
    extern __shared__ float sm[];
    float* Vbs  = sm;            // 128 j-rows of this half
    float* Us   = sm + HUS_OFF;
    float* as_  = sm + HAS_OFF;
    float* Qs   = sm + HQS_OFF;  // this half's Q
    float* Ps   = sm + HPS_OFF;
    float* sred = sm + HSR_OFF;
    float* ws   = sm + HWS_OFF;  // raw exp weights, ws[jl*36 + il]

    const int tid = threadIdx.x;
    const int b   = blockIdx.y;
    const int jh  = blockIdx.z;          // j-half
    const int igbase = blockIdx.x * 32;
    const int jgbase = jh * 128;

    // ---- stage Vb half, 32 U rows, a, Q-half, P ----
    {
        const float4* vg4  = (const float4*)g_Vb + (b*K_ + jgbase) * (D_/4);
        float4*       vbs4 = (float4*)Vbs;
        for (int idx = tid; idx < 128*D_/4; idx += 512) {
            const int j = idx >> 5, c = idx & 31;
            vbs4[j*33 + c] = vg4[idx];
        }
        const float4* ug4 = (const float4*)g_U + (b*K_ + igbase) * (D_/4);
        float4*       us4 = (float4*)Us;
        for (int idx = tid; idx < 32*D_/4; idx += 512) {
            const int il = idx >> 5, c = idx & 31;
            us4[il*33 + c] = ug4[idx];
        }
        if (tid < 128) as_[tid] = a[tid];
        else if (tid < 256) Qs[tid - 128] = g_Q[b*K_ + jgbase + tid - 128];
        else if (tid < 288) Ps[tid - 256] = g_P[b*K_ + igbase + tid - 256];
    }

    const int w  = tid >> 5;         // 0..15
    const int l  = tid & 31;         // lane = local i row
    const int j0 = w * 8;            // warp's local j chunk

    const float4* brow4 = (const float4*)(bias + (igbase + l)*K_ + jgbase + j0);
    const float4 bv0 = __ldg(brow4);
    const float4 bv1 = __ldg(brow4 + 1);

    __syncthreads();   // B1

    // ---- e-loop: acc[jj] = packed sum_d a_d * |u_{l,d} + vb_{j0+jj,d}| ----
    u64 acc[8];
    #pragma unroll
    for (int jj = 0; jj < 8; jj++) acc[jj] = 0ull;

    {
        const ulonglong2* vbs2 = (const ulonglong2*)Vbs;
        const ulonglong2* us2  = (const ulonglong2*)Us;
        const ulonglong2* a2   = (const ulonglong2*)as_;
        for (int dc = 0; dc < 32; dc++) {
            const ulonglong2 uv = us2[l*33 + dc];
            const ulonglong2 av = a2[dc];
            ulonglong2 vv[8];
            #pragma unroll
            for (int jj = 0; jj < 8; jj++) vv[jj] = vbs2[(j0 + jj)*33 + dc];
            #pragma unroll
            for (int jj = 0; jj < 8; jj++) {
                u64 z;
                z = addx2(uv.x, vv[jj].x); acc[jj] = fmax2p(av.x, z & ABSMASK2, acc[jj]);
                z = addx2(uv.y, vv[jj].y); acc[jj] = fmax2p(av.y, z & ABSMASK2, acc[jj]);
            }
        }
    }

    // ---- raw exp weights + warp-partial sums ----
    {
        const float P = Ps[l];
        const float bb[8] = {bv0.x, bv0.y, bv0.z, bv0.w, bv1.x, bv1.y, bv1.z, bv1.w};
        float s = 0.f;
        float e[8];
        #pragma unroll
        for (int jj = 0; jj < 8; jj++) {
            const float A  = lo32(acc[jj]) + hi32(acc[jj]);
            const float ev = fmaf(C_LIN, P + Qs[j0 + jj], fmaf(C_ABS, A, bb[jj]));
            e[jj] = __expf(ev);
            s += e[jj];
        }
        sred[w*32 + l] = s;
        #pragma unroll
        for (int jj = 0; jj < 8; jj++)
            ws[(j0 + jj)*36 + l] = e[jj];
    }
    __syncthreads();   // B2 — Vbs dead

    // ---- overlay x[b, this j-half] onto dead Vbs ----
    {
        float4*       xs4 = (float4*)sm;
        const float4* xg4 = (const float4*)x + (b*K_ + jgbase) * (T_/4);
        for (int idx = tid; idx < 128*T_/4; idx += 512) xs4[idx] = xg4[idx];
    }
    __syncthreads();   // B3

    // ---- epilogue stage 1: warp = (4 i's, 64 of the 128 j); -> hred ----
    u64* hred = (u64*)(sm + HHR_OFF);    // hred[(i*2 + c)*33 + l]
    {
        const int g = w & 7;             // i-group: i = 4g..4g+3
        const int c = w >> 3;            // local j chunk [64c, 64c+64)
        const u64* xs2 = (const u64*)sm;
        u64 h[4] = {0ull, 0ull, 0ull, 0ull};
        const int jbeg = 64*c;
        #pragma unroll 8
        for (int j = jbeg; j < jbeg + 64; j++) {
            const u64    xv = xs2[j*32 + l];
            const float4 wq = *(const float4*)(ws + j*36 + 4*g);   // broadcast
            h[0] = fmax2p(dup2(wq.x), xv, h[0]);
            h[1] = fmax2p(dup2(wq.y), xv, h[1]);
            h[2] = fmax2p(dup2(wq.z), xv, h[2]);
            h[3] = fmax2p(dup2(wq.w), xv, h[3]);
        }
        #pragma unroll
        for (int ii = 0; ii < 4; ii++)
            hred[((4*g + ii)*2 + c)*33 + l] = h[ii];
    }
    __syncthreads();   // B4

    // ---- stage 2: warp w -> i rows {w, w+16}; combine + store partials ----
    #pragma unroll
    for (int rep = 0; rep < 2; rep++) {
        const int i = w + 16*rep;
        u64 h = addx2(hred[(i*2 + 0)*33 + l], hred[(i*2 + 1)*33 + l]);
        float S = sred[i];
        #pragma unroll
        for (int wp = 1; wp < 16; wp++) S += sred[wp*32 + i];
        const int row = b*K_ + igbase + i;
        float2 o; o.x = lo32(h); o.y = hi32(h);
        *(float2*)(g_Hp + jh*(B_*K_*T_) + row*T_ + 2*l) = o;
        if (l == 0) g_Sp[jh*(B_*K_) + row] = S;
    }
}

// ---------------------------------------------------------------------------
// Kernel C: combine halves, normalize, sigmoid. 128 blocks x 512 thr.
// ---------------------------------------------------------------------------
__global__ void __launch_bounds__(512)
kC(float* __restrict__ out)
{
    const int gid = blockIdx.x * 512 + threadIdx.x;     // 65536 float4s
    const float4 h0 = ((const float4*)g_Hp)[gid];
    const float4 h1 = ((const float4*)g_Hp)[gid + (B_*K_*T_/4)];
    const int row = gid >> 4;
    const float inv = __fdividef(1.f, g_Sp[row] + g_Sp[B_*K_ + row]);
    float4 o;
    o.x = __fdividef(1.f, 1.f + __expf(-(h0.x + h1.x) * inv));
    o.y = __fdividef(1.f, 1.f + __expf(-(h0.y + h1.y) * inv));
    o.z = __fdividef(1.f, 1.f + __expf(-(h0.z + h1.z) * inv));
    o.w = __fdividef(1.f, 1.f + __expf(-(h0.w + h1.w) * inv));
    ((float4*)out)[gid] = o;
}

// ---------------------------------------------------------------------------
extern "C" void kernel_launch(void* const* d_in, const int* in_sizes, int n_in,
                              void* d_out, int out_size)
{
    const float* x     = (const float*)d_in[0];
    // d_in[1] = embedding (unused by the reference computation)
    const float* W     = (const float*)d_in[2];
    const float* b_lin = (const float*)d_in[3];
    const float* a     = (const float*)d_in[4];
    const float* bias  = (const float*)d_in[5];
    float* out = (float*)d_out;

    const int smemA  = KA_SMEM_FLOATS * 4;   // 81216 B
    const int smemB1 = B1_SMEM_FLOATS * 4;   // 106112 B
    cudaFuncSetAttribute(kA,  cudaFuncAttributeMaxDynamicSharedMemorySize, smemA);
    cudaFuncSetAttribute(kB1, cudaFuncAttributeMaxDynamicSharedMemorySize, smemB1);

    kA<<<128, 512, smemA>>>(x, W, b_lin, a);
    kB1<<<dim3(8, 16, 2), 512, smemB1>>>(x, a, bias);
    kC<<<128, 512>>>(out);
}

// round 13
// speedup vs baseline: 1.0498x; 1.0043x over previous
#include <cuda_runtime.h>
#include <cuda_bf16.h>

typedef unsigned long long u64;

// Problem constants
#define B_   16
#define K_   256
#define T_   64
#define D_   128
// e = C_LIN*(P+Q) + C_ABS*sum_d a_d*|u+vb| + bias   (alpha = 0.2)
#define C_LIN 0.6f
#define C_ABS 0.4f
#define ABSMASK2 0x7FFFFFFF7FFFFFFFULL

__device__ __forceinline__ u64 addx2(u64 a, u64 b) {
    u64 r; asm("add.rn.f32x2 %0,%1,%2;" : "=l"(r) : "l"(a), "l"(b)); return r;
}
__device__ __forceinline__ u64 fmax2p(u64 a, u64 b, u64 c) {
    u64 r; asm("fma.rn.f32x2 %0,%1,%2,%3;" : "=l"(r) : "l"(a), "l"(b), "l"(c)); return r;
}
__device__ __forceinline__ u64 dup2(float v) {
    u64 r; asm("mov.b64 %0, {%1, %1};" : "=l"(r) : "f"(v)); return r;
}
__device__ __forceinline__ u64 pack2(float lo, float hi) {
    u64 r; asm("mov.b64 %0, {%1, %2};" : "=l"(r) : "f"(lo), "f"(hi)); return r;
}
__device__ __forceinline__ float lo32(u64 v) { return __uint_as_float((unsigned)v); }
__device__ __forceinline__ float hi32(u64 v) { return __uint_as_float((unsigned)(v >> 32)); }

// Scratch (device globals: allocation-free rule)
__device__ float g_U  [B_*K_*D_];     // u[b,k,d]
__device__ float g_Vb [B_*K_*D_];     // v[b,k,d] + b_lin[d]
__device__ float g_PQp[4*B_*K_];      // P/Q partials: [0]+[1]=P, [2]+[3]=Q

// ---------------------------------------------------------------------------
// Kernel A v5: quarter-tiles for occupancy. Block = 32 rows x 64 cols.
// blockIdx.x = rb*4 + q; q in {0,1}: U cols [64q,64q+64); {2,3}: V likewise.
// 512 blocks x 256 threads, smem 27.4 KB -> ~3.5 blocks/SM resident.
// lane = row, warp = 8 cols (broadcast W reads from smem).
// ---------------------------------------------------------------------------
#define QWS 68
#define QXT 33
#define QOB 65
#define KAV5_WQ_OFF 0
#define KAV5_XT_OFF (64*QWS)                 // 4352
#define KAV5_AS_OFF (KAV5_XT_OFF + 64*QXT)   // 6464
#define KAV5_BL_OFF (KAV5_AS_OFF + 64)       // 6528
#define KAV5_RD_OFF (KAV5_BL_OFF + 64)       // 6592
#define KAV5_SMEM_FLOATS (KAV5_RD_OFF + 8*33)  // 6856 floats = 27424 B

__global__ void __launch_bounds__(256, 4)
kA(const float* __restrict__ x, const float* __restrict__ W,
   const float* __restrict__ b_lin, const float* __restrict__ a)
{
    extern __shared__ float sm[];
    float* Wq  = sm + KAV5_WQ_OFF;   // 64 x 68
    float* xst = sm + KAV5_XT_OFF;   // xst[k*33 + row]
    float* asQ = sm + KAV5_AS_OFF;   // 64
    float* bls = sm + KAV5_BL_OFF;   // 64 (V quarters only)
    float* red = sm + KAV5_RD_OFF;   // 8 x 33
    float* outB = sm;                // overlay on Wq after main loop (32 x 65)

    const int tid  = threadIdx.x;
    const int q    = blockIdx.x & 3;
    const int rb   = blockIdx.x >> 2;
    const int row0 = rb * 32;
    const int doff = (q & 1) * 64;       // d-offset of this quarter's cols
    const int toff = (q >= 2) ? 64 : 0;  // W column half (U vs V)

    for (int idx = tid; idx < 64*64; idx += 256) {
        const int c = idx >> 6, t = idx & 63;
        Wq[c*QWS + t] = W[(doff + c)*128 + toff + t];
    }
    for (int idx = tid; idx < 32*64; idx += 256) {
        const int r = idx >> 6, k = idx & 63;
        xst[k*QXT + r] = x[(row0 + r)*T_ + k];
    }
    if (tid < 64) asQ[tid] = a[doff + tid];
    else if (tid >= 64 && tid < 128 && q >= 2) bls[tid - 64] = b_lin[doff + tid - 64];
    __syncthreads();

    const int l  = tid & 31;     // lane = local row
    const int w  = tid >> 5;     // warp -> local cols [8w, 8w+8)
    const int c0 = w * 8;

    u64 acc[8];
    #pragma unroll
    for (int cc = 0; cc < 8; cc++) acc[cc] = 0ull;

    #pragma unroll 4
    for (int k4 = 0; k4 < 16; k4++) {
        const u64 xp01 = pack2(xst[(4*k4 + 0)*QXT + l], xst[(4*k4 + 1)*QXT + l]);
        const u64 xp23 = pack2(xst[(4*k4 + 2)*QXT + l], xst[(4*k4 + 3)*QXT + l]);
        #pragma unroll
        for (int cc = 0; cc < 8; cc++) {
            const ulonglong2 wv = *(const ulonglong2*)(Wq + (c0 + cc)*QWS + 4*k4);
            acc[cc] = fmax2p(xp01, wv.x, acc[cc]);
            acc[cc] = fmax2p(xp23, wv.y, acc[cc]);
        }
    }
    __syncthreads();   // all Wq reads done before outB overlay

    // finalize: b_lin for V quarters, per-warp P/Q partial, stash to outB
    {
        float pq = 0.f;
        #pragma unroll
        for (int cc = 0; cc < 8; cc++) {
            const int c = c0 + cc;
            float sv = lo32(acc[cc]) + hi32(acc[cc]);
            if (q >= 2) sv += bls[c];
            outB[l*QOB + c] = sv;          // bank (l + c) mod 32: conflict-free
            pq = fmaf(asQ[c], sv, pq);
        }
        red[w*33 + l] = pq;
    }
    __syncthreads();

    if (tid < 32) {
        float s = 0.f;
        #pragma unroll
        for (int ww = 0; ww < 8; ww++) s += red[ww*33 + tid];
        g_PQp[q*(B_*K_) + row0 + tid] = s;
    }

    // coalesced writeback of this quarter
    {
        float* dst = (q < 2) ? g_U : g_Vb;
        for (int idx = tid; idx < 32*64; idx += 256) {
            const int r = idx >> 6, c = idx & 63;
            dst[(row0 + r)*D_ + doff + c] = outB[r*QOB + c];
        }
    }
}

// ---------------------------------------------------------------------------
// Kernel B (monolithic, best-measured R8 version): transposed e-loop
// (32 warps, dc unrolled x2), split epilogue, x-overlay merged into the
// softmax phase. Grid (8,16) x 1024 threads.
// ---------------------------------------------------------------------------
#define VBS_F   (K_*132)                   // 33792
#define US_OFF  (VBS_F)                    // 33792
#define AS_OFF  (US_OFF + 32*132)          // 38016
#define QS_OFF  (AS_OFF + 128)             // 38144
#define PS_OFF  (QS_OFF + 256)             // 38400
#define MR_OFF  (PS_OFF + 32)              // 38432
#define SR_OFF  (MR_OFF + 1024)            // 39456
#define WS_OFF  (SR_OFF + 1024)            // 40480
#define KB_SMEM_FLOATS (WS_OFF + K_*36)    // 49696 floats = 198784 B
#define HR_OFF  16384                      // hred overlay in dead Vbs region

__global__ void __launch_bounds__(1024)
kB(const float* __restrict__ x, const float* __restrict__ a,
   const float* __restrict__ bias, float* __restrict__ out)
{
    extern __shared__ float sm[];
    float* Vbs  = sm;
    float* Us   = sm + US_OFF;
    float* as_  = sm + AS_OFF;
    float* Qs   = sm + QS_OFF;
    float* Ps   = sm + PS_OFF;
    float* mred = sm + MR_OFF;
    float* sred = sm + SR_OFF;
    float* ws   = sm + WS_OFF;   // ws[j*36 + il]

    const int tid = threadIdx.x;
    const int b   = blockIdx.y;
    const int igbase = blockIdx.x * 32;

    // ---- stage Vb[b], 32 U rows, a, Q, P (P/Q summed from quarter partials)
    {
        const float4* vg4  = (const float4*)g_Vb + b * (K_*D_/4);
        float4*       vbs4 = (float4*)Vbs;
        for (int idx = tid; idx < K_*D_/4; idx += 1024) {
            const int j = idx >> 5, c = idx & 31;
            vbs4[j*33 + c] = vg4[idx];
        }
        const float4* ug4 = (const float4*)g_U + (b*K_ + igbase) * (D_/4);
        float4*       us4 = (float4*)Us;
        for (int idx = tid; idx < 32*D_/4; idx += 1024) {
            const int il = idx >> 5, c = idx & 31;
            us4[il*33 + c] = ug4[idx];
        }
        if (tid < 128) as_[tid] = a[tid];
        else if (tid >= 256 && tid < 512) {
            const int j = tid - 256;
            Qs[j] = g_PQp[2*(B_*K_) + b*K_ + j] + g_PQp[3*(B_*K_) + b*K_ + j];
        } else if (tid >= 512 && tid < 544) {
            const int il = tid - 512;
            Ps[il] = g_PQp[0*(B_*K_) + b*K_ + igbase + il]
                   + g_PQp[1*(B_*K_) + b*K_ + igbase + il];
        }
    }

    const int w  = tid >> 5;
    const int l  = tid & 31;           // lane = local i row
    const int j0 = w * 8;              // warp's j chunk (8 rows)

    // bias prefetch (latency hidden under barrier + e-loop)
    const float4* brow4 = (const float4*)(bias + (igbase + l)*K_ + j0);
    const float4 bv0 = __ldg(brow4);
    const float4 bv1 = __ldg(brow4 + 1);

    __syncthreads();   // B1

    // ---- e-loop (dc unrolled x2): acc[jj] = sum_d a_d*|u_{l,d}+vb_{jj,d}| --
    u64 acc[8];
    #pragma unroll
    for (int jj = 0; jj < 8; jj++) acc[jj] = 0ull;

    {
        const ulonglong2* vbs2 = (const ulonglong2*)Vbs;   // row stride 33
        const ulonglong2* us2  = (const ulonglong2*)Us;
        const ulonglong2* a2   = (const ulonglong2*)as_;
        for (int dc = 0; dc < 32; dc += 2) {
            const ulonglong2 uv0 = us2[l*33 + dc];
            const ulonglong2 uv1 = us2[l*33 + dc + 1];
            const ulonglong2 av0 = a2[dc];
            const ulonglong2 av1 = a2[dc + 1];
            #pragma unroll
            for (int jj = 0; jj < 8; jj++) {
                const ulonglong2 vv0 = vbs2[(j0 + jj)*33 + dc];
                const ulonglong2 vv1 = vbs2[(j0 + jj)*33 + dc + 1];
                u64 z;
                z = addx2(uv0.x, vv0.x); acc[jj] = fmax2p(av0.x, z & ABSMASK2, acc[jj]);
                z = addx2(uv0.y, vv0.y); acc[jj] = fmax2p(av0.y, z & ABSMASK2, acc[jj]);
                z = addx2(uv1.x, vv1.x); acc[jj] = fmax2p(av1.x, z & ABSMASK2, acc[jj]);
                z = addx2(uv1.y, vv1.y); acc[jj] = fmax2p(av1.y, z & ABSMASK2, acc[jj]);
            }
        }
    }

    // ---- finish e for (i=l, j=j0..j0+8) ----
    float e[8];
    {
        const float P = Ps[l];
        const float bb[8] = {bv0.x, bv0.y, bv0.z, bv0.w, bv1.x, bv1.y, bv1.z, bv1.w};
        float m = -1e30f;
        #pragma unroll
        for (int jj = 0; jj < 8; jj++) {
            const float A  = lo32(acc[jj]) + hi32(acc[jj]);
            const float ev = fmaf(C_LIN, P + Qs[j0 + jj], fmaf(C_ABS, A, bb[jj]));
            e[jj] = ev;
            m = fmaxf(m, ev);
        }
        mred[w*32 + l] = m;
    }
    __syncthreads();   // B2 — Vbs dead from here on

    // ---- combine max, exp, sred; overlap x[b] overlay onto dead Vbs ----
    {
        float M = mred[l];
        #pragma unroll
        for (int wp = 1; wp < 32; wp++) M = fmaxf(M, mred[wp*32 + l]);
        float s = 0.f;
        #pragma unroll
        for (int jj = 0; jj < 8; jj++) { e[jj] = __expf(e[jj] - M); s += e[jj]; }
        sred[w*32 + l] = s;
        float4*       xs4 = (float4*)sm;
        const float4* xg4 = (const float4*)x + b * (K_*T_/4);
        for (int idx = tid; idx < K_*T_/4; idx += 1024) xs4[idx] = xg4[idx];
    }
    __syncthreads();   // B3

    {
        float S = sred[l];
        #pragma unroll
        for (int wp = 1; wp < 32; wp++) S += sred[wp*32 + l];
        const float inv = __fdividef(1.f, S);
        #pragma unroll
        for (int jj = 0; jj < 8; jj++)
            ws[(j0 + jj)*36 + l] = e[jj] * inv;
    }
    __syncthreads();   // B4

    // ---- epilogue stage 1: warp = (4 i's, 64 j's); partials -> hred ----
    u64* hred = (u64*)(sm + HR_OFF);   // hred[(i*4 + c)*33 + l]
    {
        const int g  = w & 7;          // i-group: i = 4g..4g+3
        const int c  = w >> 3;         // j-chunk: [64c, 64c+64)
        const u64* xs2 = (const u64*)sm;
        u64 h[4] = {0ull, 0ull, 0ull, 0ull};
        const int jbeg = 64*c;
        #pragma unroll 8
        for (int j = jbeg; j < jbeg + 64; j++) {
            const u64    xv = xs2[j*32 + l];
            const float4 wq = *(const float4*)(ws + j*36 + 4*g);   // broadcast
            h[0] = fmax2p(dup2(wq.x), xv, h[0]);
            h[1] = fmax2p(dup2(wq.y), xv, h[1]);
            h[2] = fmax2p(dup2(wq.z), xv, h[2]);
            h[3] = fmax2p(dup2(wq.w), xv, h[3]);
        }
        #pragma unroll
        for (int ii = 0; ii < 4; ii++)
            hred[((4*g + ii)*4 + c)*33 + l] = h[ii];
    }
    __syncthreads();   // B5

    // ---- epilogue stage 2: warp w -> i row w; combine 4 partials ----
    {
        u64 h = hred[(w*4 + 0)*33 + l];
        h = addx2(h, hred[(w*4 + 1)*33 + l]);
        h = addx2(h, hred[(w*4 + 2)*33 + l]);
        h = addx2(h, hred[(w*4 + 3)*33 + l]);
        const int row = (b*K_ + igbase + w)*T_ + 2*l;
        float2 o;
        o.x = __fdividef(1.f, 1.f + __expf(-lo32(h)));
        o.y = __fdividef(1.f, 1.f + __expf(-hi32(h)));
        *(float2*)(out + row) = o;
    }
}

// ---------------------------------------------------------------------------
extern "C" void kernel_launch(void* const* d_in, const int* in_sizes, int n_in,
                              void* d_out, int out_size)
{
    const float* x     = (const float*)d_in[0];
    // d_in[1] = embedding (unused by the reference computation)
    const float* W     = (const float*)d_in[2];
    const float* b_lin = (const float*)d_in[3];
    const float* a     = (const float*)d_in[4];
    const float* bias  = (const float*)d_in[5];
    float* out = (float*)d_out;

    const int smemA = KAV5_SMEM_FLOATS * 4;  // 27424 B
    const int smemB = KB_SMEM_FLOATS * 4;    // 198784 B
    cudaFuncSetAttribute(kA, cudaFuncAttributeMaxDynamicSharedMemorySize, smemA);
    cudaFuncSetAttribute(kB, cudaFuncAttributeMaxDynamicSharedMemorySize, smemB);

    kA<<<512, 256, smemA>>>(x, W, b_lin, a);
    kB<<<dim3(8, 16), 1024, smemB>>>(x, a, bias, out);
}

// round 14
// speedup vs baseline: 1.0797x; 1.0285x over previous
#include <cuda_runtime.h>
#include <cuda_bf16.h>

typedef unsigned long long u64;

// Problem constants
#define B_   16
#define K_   256
#define T_   64
#define D_   128
// e = C_LIN*(P+Q) + C_ABS*sum_d a_d*|u+vb| + bias   (alpha = 0.2)
#define C_LIN 0.6f
#define C_ABS 0.4f
#define ABSMASK2 0x7FFFFFFF7FFFFFFFULL

__device__ __forceinline__ u64 addx2(u64 a, u64 b) {
    u64 r; asm("add.rn.f32x2 %0,%1,%2;" : "=l"(r) : "l"(a), "l"(b)); return r;
}
__device__ __forceinline__ u64 fmax2p(u64 a, u64 b, u64 c) {
    u64 r; asm("fma.rn.f32x2 %0,%1,%2,%3;" : "=l"(r) : "l"(a), "l"(b), "l"(c)); return r;
}
__device__ __forceinline__ u64 dup2(float v) {
    u64 r; asm("mov.b64 %0, {%1, %1};" : "=l"(r) : "f"(v)); return r;
}
__device__ __forceinline__ u64 pack2(float lo, float hi) {
    u64 r; asm("mov.b64 %0, {%1, %2};" : "=l"(r) : "f"(lo), "f"(hi)); return r;
}
__device__ __forceinline__ float lo32(u64 v) { return __uint_as_float((unsigned)v); }
__device__ __forceinline__ float hi32(u64 v) { return __uint_as_float((unsigned)(v >> 32)); }

// Scratch (device globals: allocation-free rule)
__device__ float g_U [B_*K_*D_];   // u[b,k,d]
__device__ float g_Vb[B_*K_*D_];   // v[b,k,d] + b_lin[d]
__device__ float g_P [B_*K_];      // sum_d a_d * u
__device__ float g_Q [B_*K_];      // sum_d a_d * vb

// ---------------------------------------------------------------------------
// Kernel A v6: v3 tile (32 rows x 256 cols, smem-W broadcast) at 1024
// threads / 32 warps. lane = row, warp w -> cols [8w, 8w+8).
// 128 blocks, smem 81 KB (1 block/SM, 8 warps/SMSP).
// ---------------------------------------------------------------------------
#define WS_STRIDE 68
#define XT_STRIDE 33
#define OB_STRIDE 257
#define KA_W_F    (256*WS_STRIDE)            // 17408
#define KA_XT_OFF (KA_W_F)                   // 64 x 33 = 2112
#define KA_AS_OFF (KA_XT_OFF + 64*XT_STRIDE) // 19520
#define KA_BL_OFF (KA_AS_OFF + 128)          // 19648
#define KA_RP_OFF (KA_BL_OFF + 128)          // 19776  (16 x 33)
#define KA_RQ_OFF (KA_RP_OFF + 16*33)        // 20304
#define KA_SMEM_FLOATS (KA_RQ_OFF + 16*33)   // 20832 floats = 83328 B

__global__ void __launch_bounds__(1024)
kA(const float* __restrict__ x, const float* __restrict__ W,
   const float* __restrict__ b_lin, const float* __restrict__ a)
{
    extern __shared__ float sm[];
    float* Ws   = sm;                 // Wr[c][t], c<128 -> W1 cols, else W2
    float* xst  = sm + KA_XT_OFF;     // xst[k*33 + row]
    float* asA  = sm + KA_AS_OFF;
    float* bls  = sm + KA_BL_OFF;
    float* redP = sm + KA_RP_OFF;
    float* redQ = sm + KA_RQ_OFF;
    float* outB = sm;                 // overlay on Ws after main loop

    const int tid  = threadIdx.x;
    const int row0 = blockIdx.x * 32;

    for (int idx = tid; idx < 256*64; idx += 1024) {
        const int n = idx >> 6, t = idx & 63;
        Ws[n*WS_STRIDE + t] = (n < 128) ? W[n*128 + t] : W[(n-128)*128 + 64 + t];
    }
    for (int idx = tid; idx < 32*64; idx += 1024) {
        const int r = idx >> 6, k = idx & 63;
        xst[k*XT_STRIDE + r] = x[(row0 + r)*T_ + k];
    }
    if (tid < 128) asA[tid] = a[tid];
    else if (tid >= 256 && tid < 384) bls[tid - 256] = b_lin[tid - 256];
    __syncthreads();

    const int l  = tid & 31;       // lane = local row
    const int w  = tid >> 5;       // warp -> cols [8w, 8w+8)
    const int c0 = w * 8;

    u64 acc[8];
    #pragma unroll
    for (int cc = 0; cc < 8; cc++) acc[cc] = 0ull;

    #pragma unroll 4
    for (int k4 = 0; k4 < 16; k4++) {
        const u64 xp01 = pack2(xst[(4*k4 + 0)*XT_STRIDE + l],
                               xst[(4*k4 + 1)*XT_STRIDE + l]);
        const u64 xp23 = pack2(xst[(4*k4 + 2)*XT_STRIDE + l],
                               xst[(4*k4 + 3)*XT_STRIDE + l]);
        #pragma unroll
        for (int cc = 0; cc < 8; cc++) {
            const ulonglong2 wv = *(const ulonglong2*)(Ws + (c0 + cc)*WS_STRIDE + 4*k4);
            acc[cc] = fmax2p(xp01, wv.x, acc[cc]);
            acc[cc] = fmax2p(xp23, wv.y, acc[cc]);
        }
    }
    __syncthreads();   // all Ws reads done before outB overlay

    // finalize: add b_lin for V-cols, P/Q partials, stash to outB (stride 257)
    {
        float pq = 0.f;
        const bool isV = (w >= 16);
        #pragma unroll
        for (int cc = 0; cc < 8; cc++) {
            const int c  = c0 + cc;
            float sv = lo32(acc[cc]) + hi32(acc[cc]);
            if (isV) sv += bls[c - 128];
            outB[l*OB_STRIDE + c] = sv;
            pq = fmaf(asA[c & 127], sv, pq);
        }
        if (isV) redQ[(w - 16)*33 + l] = pq;
        else     redP[w*33 + l]        = pq;
    }
    __syncthreads();

    // P/Q combine
    if (tid < 32) {
        float p = 0.f;
        #pragma unroll
        for (int ww = 0; ww < 16; ww++) p += redP[ww*33 + tid];
        g_P[row0 + tid] = p;
    } else if (tid < 64) {
        const int r = tid - 32;
        float q = 0.f;
        #pragma unroll
        for (int ww = 0; ww < 16; ww++) q += redQ[ww*33 + r];
        g_Q[row0 + r] = q;
    }

    // coalesced writeback
    for (int idx = tid; idx < 32*256; idx += 1024) {
        const int r = idx >> 8, c = idx & 255;
        const float val = outB[r*OB_STRIDE + c];
        if (c < 128) g_U [(row0 + r)*D_ + c]       = val;
        else         g_Vb[(row0 + r)*D_ + c - 128] = val;
    }
}

// ---------------------------------------------------------------------------
// Kernel B (frozen R13 monolithic): transposed e-loop (32 warps, dc x2),
// split epilogue, x-overlay merged into softmax. Grid (8,16) x 1024.
// ---------------------------------------------------------------------------
#define VBS_F   (K_*132)                   // 33792
#define US_OFF  (VBS_F)                    // 33792
#define AS_OFF  (US_OFF + 32*132)          // 38016
#define QS_OFF  (AS_OFF + 128)             // 38144
#define PS_OFF  (QS_OFF + 256)             // 38400
#define MR_OFF  (PS_OFF + 32)              // 38432
#define SR_OFF  (MR_OFF + 1024)            // 39456
#define WSB_OFF (SR_OFF + 1024)            // 40480
#define KB_SMEM_FLOATS (WSB_OFF + K_*36)   // 49696 floats = 198784 B
#define HR_OFF  16384                      // hred overlay in dead Vbs region

__global__ void __launch_bounds__(1024)
kB(const float* __restrict__ x, const float* __restrict__ a,
   const float* __restrict__ bias, float* __restrict__ out)
{
    extern __shared__ float sm[];
    float* Vbs  = sm;
    float* Us   = sm + US_OFF;
    float* as_  = sm + AS_OFF;
    float* Qs   = sm + QS_OFF;
    float* Ps   = sm + PS_OFF;
    float* mred = sm + MR_OFF;
    float* sred = sm + SR_OFF;
    float* ws   = sm + WSB_OFF;  // ws[j*36 + il]

    const int tid = threadIdx.x;
    const int b   = blockIdx.y;
    const int igbase = blockIdx.x * 32;

    // ---- stage Vb[b], 32 U rows, a, Q, P ----
    {
        const float4* vg4  = (const float4*)g_Vb + b * (K_*D_/4);
        float4*       vbs4 = (float4*)Vbs;
        for (int idx = tid; idx < K_*D_/4; idx += 1024) {
            const int j = idx >> 5, c = idx & 31;
            vbs4[j*33 + c] = vg4[idx];
        }
        const float4* ug4 = (const float4*)g_U + (b*K_ + igbase) * (D_/4);
        float4*       us4 = (float4*)Us;
        for (int idx = tid; idx < 32*D_/4; idx += 1024) {
            const int il = idx >> 5, c = idx & 31;
            us4[il*33 + c] = ug4[idx];
        }
        if (tid < 128) as_[tid] = a[tid];
        else if (tid >= 256 && tid < 512) Qs[tid - 256] = g_Q[b*K_ + tid - 256];
        else if (tid >= 512 && tid < 544) Ps[tid - 512] = g_P[b*K_ + igbase + tid - 512];
    }

    const int w  = tid >> 5;
    const int l  = tid & 31;           // lane = local i row
    const int j0 = w * 8;              // warp's j chunk (8 rows)

    const float4* brow4 = (const float4*)(bias + (igbase + l)*K_ + j0);
    const float4 bv0 = __ldg(brow4);
    const float4 bv1 = __ldg(brow4 + 1);

    __syncthreads();   // B1

    // ---- e-loop (dc unrolled x2) ----
    u64 acc[8];
    #pragma unroll
    for (int jj = 0; jj < 8; jj++) acc[jj] = 0ull;

    {
        const ulonglong2* vbs2 = (const ulonglong2*)Vbs;   // row stride 33
        const ulonglong2* us2  = (const ulonglong2*)Us;
        const ulonglong2* a2   = (const ulonglong2*)as_;
        for (int dc = 0; dc < 32; dc += 2) {
            const ulonglong2 uv0 = us2[l*33 + dc];
            const ulonglong2 uv1 = us2[l*33 + dc + 1];
            const ulonglong2 av0 = a2[dc];
            const ulonglong2 av1 = a2[dc + 1];
            #pragma unroll
            for (int jj = 0; jj < 8; jj++) {
                const ulonglong2 vv0 = vbs2[(j0 + jj)*33 + dc];
                const ulonglong2 vv1 = vbs2[(j0 + jj)*33 + dc + 1];
                u64 z;
                z = addx2(uv0.x, vv0.x); acc[jj] = fmax2p(av0.x, z & ABSMASK2, acc[jj]);
                z = addx2(uv0.y, vv0.y); acc[jj] = fmax2p(av0.y, z & ABSMASK2, acc[jj]);
                z = addx2(uv1.x, vv1.x); acc[jj] = fmax2p(av1.x, z & ABSMASK2, acc[jj]);
                z = addx2(uv1.y, vv1.y); acc[jj] = fmax2p(av1.y, z & ABSMASK2, acc[jj]);
            }
        }
    }

    // ---- finish e ----
    float e[8];
    {
        const float P = Ps[l];
        const float bb[8] = {bv0.x, bv0.y, bv0.z, bv0.w, bv1.x, bv1.y, bv1.z, bv1.w};
        float m = -1e30f;
        #pragma unroll
        for (int jj = 0; jj < 8; jj++) {
            const float A  = lo32(acc[jj]) + hi32(acc[jj]);
            const float ev = fmaf(C_LIN, P + Qs[j0 + jj], fmaf(C_ABS, A, bb[jj]));
            e[jj] = ev;
            m = fmaxf(m, ev);
        }
        mred[w*32 + l] = m;
    }
    __syncthreads();   // B2 — Vbs dead from here on

    // ---- combine max, exp, sred; overlap x[b] overlay ----
    {
        float M = mred[l];
        #pragma unroll
        for (int wp = 1; wp < 32; wp++) M = fmaxf(M, mred[wp*32 + l]);
        float s = 0.f;
        #pragma unroll
        for (int jj = 0; jj < 8; jj++) { e[jj] = __expf(e[jj] - M); s += e[jj]; }
        sred[w*32 + l] = s;
        float4*       xs4 = (float4*)sm;
        const float4* xg4 = (const float4*)x + b * (K_*T_/4);
        for (int idx = tid; idx < K_*T_/4; idx += 1024) xs4[idx] = xg4[idx];
    }
    __syncthreads();   // B3

    {
        float S = sred[l];
        #pragma unroll
        for (int wp = 1; wp < 32; wp++) S += sred[wp*32 + l];
        const float inv = __fdividef(1.f, S);
        #pragma unroll
        for (int jj = 0; jj < 8; jj++)
            ws[(j0 + jj)*36 + l] = e[jj] * inv;
    }
    __syncthreads();   // B4

    // ---- epilogue stage 1 ----
    u64* hred = (u64*)(sm + HR_OFF);   // hred[(i*4 + c)*33 + l]
    {
        const int g  = w & 7;
        const int c  = w >> 3;
        const u64* xs2 = (const u64*)sm;
        u64 h[4] = {0ull, 0ull, 0ull, 0ull};
        const int jbeg = 64*c;
        #pragma unroll 8
        for (int j = jbeg; j < jbeg + 64; j++) {
            const u64    xv = xs2[j*32 + l];
            const float4 wq = *(const float4*)(ws + j*36 + 4*g);   // broadcast
            h[0] = fmax2p(dup2(wq.x), xv, h[0]);
            h[1] = fmax2p(dup2(wq.y), xv, h[1]);
            h[2] = fmax2p(dup2(wq.z), xv, h[2]);
            h[3] = fmax2p(dup2(wq.w), xv, h[3]);
        }
        #pragma unroll
        for (int ii = 0; ii < 4; ii++)
            hred[((4*g + ii)*4 + c)*33 + l] = h[ii];
    }
    __syncthreads();   // B5

    // ---- epilogue stage 2 ----
    {
        u64 h = hred[(w*4 + 0)*33 + l];
        h = addx2(h, hred[(w*4 + 1)*33 + l]);
        h = addx2(h, hred[(w*4 + 2)*33 + l]);
        h = addx2(h, hred[(w*4 + 3)*33 + l]);
        const int row = (b*K_ + igbase + w)*T_ + 2*l;
        float2 o;
        o.x = __fdividef(1.f, 1.f + __expf(-lo32(h)));
        o.y = __fdividef(1.f, 1.f + __expf(-hi32(h)));
        *(float2*)(out + row) = o;
    }
}

// ---------------------------------------------------------------------------
extern "C" void kernel_launch(void* const* d_in, const int* in_sizes, int n_in,
                              void* d_out, int out_size)
{
    const float* x     = (const float*)d_in[0];
    // d_in[1] = embedding (unused by the reference computation)
    const float* W     = (const float*)d_in[2];
    const float* b_lin = (const float*)d_in[3];
    const float* a     = (const float*)d_in[4];
    const float* bias  = (const float*)d_in[5];
    float* out = (float*)d_out;

    const int smemA = KA_SMEM_FLOATS * 4;   // 83328 B
    const int smemB = KB_SMEM_FLOATS * 4;   // 198784 B
    cudaFuncSetAttribute(kA, cudaFuncAttributeMaxDynamicSharedMemorySize, smemA);
    cudaFuncSetAttribute(kB, cudaFuncAttributeMaxDynamicSharedMemorySize, smemB);

    kA<<<128, 1024, smemA>>>(x, W, b_lin, a);
    kB<<<dim3(8, 16), 1024, smemB>>>(x, a, bias, out);
}